// round 16
// baseline (speedup 1.0000x reference)
#include <cuda_runtime.h>
#include <cuda_bf16.h>
#include <math.h>
#include <stdint.h>

// Problem constants
#define Bq 2
#define Tq 2048
#define Dq 1024
#define Hq 16
#define DKq 64
#define Mq (Bq*Tq)   // 4096

// ---------------- scratch (device globals; no allocation allowed) ----------
__device__ float g_Q[Mq * Dq];
__device__ float g_V[Mq * Dq];
__device__ float g_C[Mq * Dq];
// merged hi/lo pair-interleaved buffers: per 16B group {h_e, h_o, l_e, l_o}
__device__ uint32_t g_Khl[Mq * Dq];   // K, (B,T) rows x Dq u32
__device__ uint32_t g_Vhl[Mq * Dq];   // V^T per head, (B,H,DK) rows x Tq u32

// pair permutation: dpair index p (0..31) -> j' so frag pairs (tc, tc+4) are adjacent
__device__ __forceinline__ int pair_perm(int p) {
    return ((p >> 3) << 3) + 2 * (p & 3) + ((p >> 2) & 1);
}

// ---------------- tf32 helpers ----------------------------------------------
__device__ __forceinline__ uint32_t f2tf32(float f) {
    uint32_t r;
    asm volatile("cvt.rna.tf32.f32 %0, %1;" : "=r"(r) : "f"(f));
    return r;
}

__device__ __forceinline__ void mma_tf32(float c[4],
                                         uint32_t a0, uint32_t a1, uint32_t a2, uint32_t a3,
                                         uint32_t b0, uint32_t b1) {
    asm volatile(
        "mma.sync.aligned.m16n8k8.row.col.f32.tf32.tf32.f32 "
        "{%0,%1,%2,%3}, {%4,%5,%6,%7}, {%8,%9}, {%0,%1,%2,%3};"
        : "+f"(c[0]), "+f"(c[1]), "+f"(c[2]), "+f"(c[3])
        : "r"(a0), "r"(a1), "r"(a2), "r"(a3), "r"(b0), "r"(b1));
}

// ---------------- bf16 helpers ----------------------------------------------
__device__ __forceinline__ uint32_t pack_bf16x2(float x, float y) {
    uint32_t r;
    asm("cvt.rn.bf16x2.f32 %0, %1, %2;" : "=r"(r) : "f"(y), "f"(x));
    return r;
}
__device__ __forceinline__ float bf_lo_f(uint32_t p) { return __uint_as_float(p << 16); }
__device__ __forceinline__ float bf_hi_f(uint32_t p) { return __uint_as_float(p & 0xffff0000u); }

__device__ __forceinline__ void mma_bf16(float c[4],
                                         uint32_t a0, uint32_t a1, uint32_t a2, uint32_t a3,
                                         uint32_t b0, uint32_t b1) {
    asm volatile(
        "mma.sync.aligned.m16n8k16.row.col.f32.bf16.bf16.f32 "
        "{%0,%1,%2,%3}, {%4,%5,%6,%7}, {%8,%9}, {%0,%1,%2,%3};"
        : "+f"(c[0]), "+f"(c[1]), "+f"(c[2]), "+f"(c[3])
        : "r"(a0), "r"(a1), "r"(a2), "r"(a3), "r"(b0), "r"(b1));
}

__device__ __forceinline__ float ex2f(float x) {
    float r;
    asm("ex2.approx.f32 %0, %1;" : "=f"(r) : "f"(x));
    return r;
}
#define QSCALE (0.125f * 1.4426950408889634f)   // 1/sqrt(dk) * log2(e)

// ---------------- pre-pass: V transpose-split (merged interleaved output) ----
__global__ __launch_bounds__(256)
void transpose_split_v_kernel(const float* __restrict__ V,
                              uint32_t* __restrict__ Vhl)
{
    __shared__ float tile[32][33];
    const int t0 = blockIdx.x * 32;
    const int d0 = blockIdx.y * 32;
    const int h  = blockIdx.z & (Hq - 1);
    const int b  = blockIdx.z >> 4;
    const int tx = threadIdx.x & 31, ty = threadIdx.x >> 5;

    const float* src = V + ((size_t)b * Tq + t0) * Dq + h * DKq + d0;
#pragma unroll
    for (int j = ty; j < 32; j += 8)
        tile[j][tx] = src[(size_t)j * Dq + tx];
    __syncthreads();

    // row = (b*Hq+h)*DKq + d0 + j, row stride Tq u32 = 2*Tq bf16
    __nv_bfloat16* out = (__nv_bfloat16*)(Vhl + ((size_t)(b * Hq + h) * DKq + d0) * Tq);
#pragma unroll
    for (int j = ty; j < 32; j += 8) {
        float v = tile[tx][j];               // element (t = t0+tx, d = d0+j)
        const int t  = t0 + tx;
        const int kp = (t & 63) >> 1;        // keypair within 64-key block
        const int cj = (t >> 6) * 32 + pair_perm(kp);   // u32 pair index (old layout)
        const int uh = 4 * (cj >> 1) + (cj & 1);        // merged u32 offsets
        __nv_bfloat16 hb = __float2bfloat16(v);
        out[(size_t)j * 2 * Tq + 2 * uh + (t & 1)]       = hb;
        out[(size_t)j * 2 * Tq + 2 * (uh + 2) + (t & 1)] = __float2bfloat16(v - __bfloat162float(hb));
    }
}

// ---------------- Pipelined TF32 GEMM: 128 threads, warp tile 64x64 ----------
#define GBM 128
#define GBN 128
#define GBK 16
#define SMP 136

__device__ __forceinline__ int aperm(int m) {
    return (m & ~15) | (2 * (m & 7) + ((m >> 3) & 1));
}

template <int SPLIT>
__device__ __forceinline__
void tf32_gemm_body(const float* __restrict__ X,
                    const float* __restrict__ W,
                    const float* __restrict__ bias,
                    float* __restrict__ Y,
                    uint32_t* __restrict__ Yhl,
                    int M, int N, int K,
                    int bm, int bn)
{
    __shared__ __align__(16) uint32_t As[2][GBK][SMP];
    __shared__ __align__(16) uint32_t Bs[2][GBK][SMP];

    const int tid  = threadIdx.x;      // 0..127
    const int wid  = tid >> 5;         // 0..3
    const int lane = tid & 31;
    const int gr   = lane >> 2;
    const int tc   = lane & 3;

    const int wm = wid & 1;
    const int wn = wid >> 1;

    const int a_r0 = tid >> 1;
    const int a_kc = (tid & 1) * 8;
    const int b_r0 = tid >> 4;
    const int b_c  = (tid & 15) * 4;

    const float* Xp = X + (size_t)(bm * GBM) * K;
    const float* Wp = W + (size_t)bn * GBN;

    float acc[4][8][4];
#pragma unroll
    for (int i = 0; i < 4; ++i)
#pragma unroll
        for (int j = 0; j < 8; ++j)
#pragma unroll
            for (int f = 0; f < 4; ++f) acc[i][j][f] = 0.f;

    float4 la[2][2], lb[2][2];

    auto loadTile = [&](int k0) {
#pragma unroll
        for (int q = 0; q < 2; ++q) {
            la[q][0] = *(const float4*)(Xp + (size_t)(a_r0 + q * 64) * K + k0 + a_kc);
            la[q][1] = *(const float4*)(Xp + (size_t)(a_r0 + q * 64) * K + k0 + a_kc + 4);
            lb[q][0] = *(const float4*)(Wp + (size_t)(k0 + b_r0 + q * 8) * N + b_c);
            lb[q][1] = *(const float4*)(Wp + (size_t)(k0 + b_r0 + q * 8) * N + b_c + 64);
        }
    };
    auto storeTile = [&](int s) {
#pragma unroll
        for (int q = 0; q < 2; ++q) {
            const int row = aperm(a_r0 + q * 64);
            As[s][a_kc + 0][row] = f2tf32(la[q][0].x);
            As[s][a_kc + 1][row] = f2tf32(la[q][0].y);
            As[s][a_kc + 2][row] = f2tf32(la[q][0].z);
            As[s][a_kc + 3][row] = f2tf32(la[q][0].w);
            As[s][a_kc + 4][row] = f2tf32(la[q][1].x);
            As[s][a_kc + 5][row] = f2tf32(la[q][1].y);
            As[s][a_kc + 6][row] = f2tf32(la[q][1].z);
            As[s][a_kc + 7][row] = f2tf32(la[q][1].w);
            const int br = b_r0 + q * 8;
            uint4 u0, u1;
            u0.x = f2tf32(lb[q][0].x); u0.y = f2tf32(lb[q][0].y);
            u0.z = f2tf32(lb[q][0].z); u0.w = f2tf32(lb[q][0].w);
            u1.x = f2tf32(lb[q][1].x); u1.y = f2tf32(lb[q][1].y);
            u1.z = f2tf32(lb[q][1].z); u1.w = f2tf32(lb[q][1].w);
            *(uint4*)&Bs[s][br][b_c]      = u0;
            *(uint4*)&Bs[s][br][b_c + 64] = u1;
        }
    };

    loadTile(0);
    storeTile(0);
    __syncthreads();

    int cur = 0;
    for (int k0 = 0; k0 < K; k0 += GBK) {
        const bool has_next = (k0 + GBK < K);
        if (has_next) loadTile(k0 + GBK);

#pragma unroll
        for (int ks = 0; ks < GBK; ks += 8) {
            uint32_t af[4][4];
            uint32_t bf[8][2];
#pragma unroll
            for (int mt = 0; mt < 4; ++mt) {
                int m0 = wm * 64 + mt * 16 + 2 * gr;
                uint2 p0 = *(const uint2*)&As[cur][ks + tc][m0];
                uint2 p1 = *(const uint2*)&As[cur][ks + tc + 4][m0];
                af[mt][0] = p0.x; af[mt][1] = p0.y;
                af[mt][2] = p1.x; af[mt][3] = p1.y;
            }
#pragma unroll
            for (int nt = 0; nt < 8; ++nt) {
                int n0 = wn * 64 + nt * 8;
                bf[nt][0] = Bs[cur][ks + tc][n0 + gr];
                bf[nt][1] = Bs[cur][ks + tc + 4][n0 + gr];
            }
#pragma unroll
            for (int mt = 0; mt < 4; ++mt)
#pragma unroll
                for (int nt = 0; nt < 8; ++nt)
                    mma_tf32(acc[mt][nt],
                             af[mt][0], af[mt][1], af[mt][2], af[mt][3],
                             bf[nt][0], bf[nt][1]);
        }

        if (has_next) {
            const int nxt = cur ^ 1;
            storeTile(nxt);
            __syncthreads();
            cur = nxt;
        }
    }

#pragma unroll
    for (int mt = 0; mt < 4; ++mt) {
        int row = bm * GBM + wm * 64 + mt * 16 + gr;
#pragma unroll
        for (int nt = 0; nt < 8; ++nt) {
            int col = bn * GBN + wn * 64 + nt * 8 + 2 * tc;
            float b0 = bias[col], b1 = bias[col + 1];
            float v00 = acc[mt][nt][0] + b0, v01 = acc[mt][nt][1] + b1;
            float v10 = acc[mt][nt][2] + b0, v11 = acc[mt][nt][3] + b1;
            if (SPLIT) {
                // merged interleaved layout: {h_e, h_o, l_e, l_o} per 16B group
                const int cj = (col >> 6) * 32 + pair_perm((col & 63) >> 1);
                const int uh = 4 * (cj >> 1) + (cj & 1);
                uint32_t h0 = pack_bf16x2(v00, v01);
                uint32_t l0 = pack_bf16x2(v00 - bf_lo_f(h0), v01 - bf_hi_f(h0));
                uint32_t h1 = pack_bf16x2(v10, v11);
                uint32_t l1 = pack_bf16x2(v10 - bf_lo_f(h1), v11 - bf_hi_f(h1));
                Yhl[(size_t)row * N + uh]           = h0;
                Yhl[(size_t)row * N + uh + 2]       = l0;
                Yhl[(size_t)(row + 8) * N + uh]     = h1;
                Yhl[(size_t)(row + 8) * N + uh + 2] = l1;
            } else {
                float2 lo, hi;
                lo.x = v00; lo.y = v01;
                hi.x = v10; hi.y = v11;
                *(float2*)(Y + (size_t)row * N + col)       = lo;
                *(float2*)(Y + (size_t)(row + 8) * N + col) = hi;
            }
        }
    }
}

__global__ __launch_bounds__(128, 2)
void tf32_gemm_kernel(const float* __restrict__ X,
                      const float* __restrict__ W,
                      const float* __restrict__ bias,
                      float* __restrict__ Y,
                      int M, int N, int K)
{
    tf32_gemm_body<0>(X, W, bias, Y, nullptr, M, N, K, blockIdx.y, blockIdx.x);
}

__global__ __launch_bounds__(128, 2)
void tf32_qkv_kernel(const float* __restrict__ X,
                     const float* __restrict__ Wq, const float* __restrict__ bqv,
                     const float* __restrict__ Wk, const float* __restrict__ bkv,
                     const float* __restrict__ Wv, const float* __restrict__ bvv,
                     float* __restrict__ Qo,
                     uint32_t* __restrict__ Khl,
                     float* __restrict__ Vo)
{
    if (blockIdx.z == 0)
        tf32_gemm_body<0>(X, Wq, bqv, Qo, nullptr, Mq, Dq, Dq, blockIdx.y, blockIdx.x);
    else if (blockIdx.z == 1)
        tf32_gemm_body<1>(X, Wk, bkv, nullptr, Khl, Mq, Dq, Dq, blockIdx.y, blockIdx.x);
    else
        tf32_gemm_body<0>(X, Wv, bvv, Vo, nullptr, Mq, Dq, Dq, blockIdx.y, blockIdx.x);
}

// ---------------- bf16-split flash attention (merged LDS.128 fragments) ------
// K/V arrive pre-split, pair-permuted AND hi/lo interleaved: one LDS.128
// yields {bh.x, bh.y, bl.x, bl.y}. Row stride 80 u32 = 20x16B ->
// load banks (4gr+4kk+tc)%8 distinct, fill banks (4r+j)%8 distinct.
#define AQT 64
#define AKT 64
#define KPADW 80

__global__ __launch_bounds__(128, 4)
void attn_bf_kernel(const float* __restrict__ Q,
                    const uint32_t* __restrict__ Khl,
                    const uint32_t* __restrict__ Vhl,
                    float* __restrict__ Ctx)
{
    __shared__ __align__(16) uint32_t Ksm[64 * KPADW];
    __shared__ __align__(16) uint32_t Vsm[64 * KPADW];

    const int b  = blockIdx.z;
    const int h  = blockIdx.y;
    const int qb = gridDim.x - 1 - blockIdx.x;
    const int tid  = threadIdx.x;
    const int wid  = tid >> 5;
    const int lane = tid & 31;
    const int gr   = lane >> 2;
    const int tc   = lane & 3;

    const int qrow0 = qb * AQT;
    const float* Qg = Q + ((size_t)b * Tq + qrow0) * Dq + h * DKq;

    uint32_t qh[4][4], ql[4][4];
    {
        const int rbase = wid * 16;
#pragma unroll
        for (int kk = 0; kk < 4; ++kk) {
#pragma unroll
            for (int f = 0; f < 4; ++f) {
                int r = rbase + gr + (f & 1) * 8;
                int c = kk * 16 + 2 * tc + (f >> 1) * 8;
                float2 v = *(const float2*)(Qg + (size_t)r * Dq + c);
                v.x *= QSCALE; v.y *= QSCALE;    // exp2-domain scale
                uint32_t hpk = pack_bf16x2(v.x, v.y);
                qh[kk][f] = hpk;
                ql[kk][f] = pack_bf16x2(v.x - bf_lo_f(hpk), v.y - bf_hi_f(hpk));
            }
        }
    }

    float oacc[8][4];
#pragma unroll
    for (int n = 0; n < 8; ++n)
#pragma unroll
        for (int f = 0; f < 4; ++f) oacc[n][f] = 0.f;
    float m0 = -INFINITY, m1 = -INFINITY, l0 = 0.f, l1 = 0.f;

    const int row0g = qrow0 + wid * 16 + gr;
    const int row1g = row0g + 8;
    const int kbmax = qb + 1;

    for (int kb = 0; kb < kbmax; ++kb) {
        {
            // K: rows kb*64..+63 of (b), head h -> 64 contiguous u32 per row
            const uint32_t* KG = Khl + ((size_t)b * Tq + kb * AKT) * Dq + 64 * h;
            // V: rows = (b*Hq+h)*DKq + d, 64 contiguous u32 at offset 64*kb
            const uint32_t* VG = Vhl + ((size_t)(b * Hq + h) * DKq) * Tq + 64 * kb;
#pragma unroll
            for (int i = tid; i < 1024; i += 128) {
                int r = i >> 4, j = i & 15;
                *(uint4*)&Ksm[r * KPADW + j * 4] = *(const uint4*)(KG + (size_t)r * Dq + j * 4);
                *(uint4*)&Vsm[r * KPADW + j * 4] = *(const uint4*)(VG + (size_t)r * Tq + j * 4);
            }
        }
        __syncthreads();

        {
            float sacc[8][4];
#pragma unroll
            for (int n = 0; n < 8; ++n)
#pragma unroll
                for (int f = 0; f < 4; ++f) sacc[n][f] = 0.f;

#pragma unroll
            for (int kk = 0; kk < 4; ++kk) {
#pragma unroll
                for (int n = 0; n < 8; ++n) {
                    uint4 u = *(const uint4*)&Ksm[(n * 8 + gr) * KPADW + kk * 16 + 4 * tc];
                    mma_bf16(sacc[n], qh[kk][0], qh[kk][1], qh[kk][2], qh[kk][3], u.x, u.y);
                    mma_bf16(sacc[n], ql[kk][0], ql[kk][1], ql[kk][2], ql[kk][3], u.x, u.y);
                    mma_bf16(sacc[n], qh[kk][0], qh[kk][1], qh[kk][2], qh[kk][3], u.z, u.w);
                }
            }

            if (kb == kbmax - 1) {
#pragma unroll
                for (int n = 0; n < 8; ++n) {
                    int colg = kb * AKT + n * 8 + 2 * tc;
                    if (colg     > row0g) sacc[n][0] = -INFINITY;
                    if (colg + 1 > row0g) sacc[n][1] = -INFINITY;
                    if (colg     > row1g) sacc[n][2] = -INFINITY;
                    if (colg + 1 > row1g) sacc[n][3] = -INFINITY;
                }
            }

            float rmax0 = -INFINITY, rmax1 = -INFINITY;
#pragma unroll
            for (int n = 0; n < 8; ++n) {
                rmax0 = fmaxf(rmax0, fmaxf(sacc[n][0], sacc[n][1]));
                rmax1 = fmaxf(rmax1, fmaxf(sacc[n][2], sacc[n][3]));
            }
#pragma unroll
            for (int off = 1; off < 4; off <<= 1) {
                rmax0 = fmaxf(rmax0, __shfl_xor_sync(0xffffffffu, rmax0, off));
                rmax1 = fmaxf(rmax1, __shfl_xor_sync(0xffffffffu, rmax1, off));
            }

            float mn0 = fmaxf(m0, rmax0);
            float mn1 = fmaxf(m1, rmax1);
            float alpha0 = ex2f(m0 - mn0);
            float alpha1 = ex2f(m1 - mn1);

            float rsum0 = 0.f, rsum1 = 0.f;
#pragma unroll
            for (int n = 0; n < 8; ++n) {
                sacc[n][0] = ex2f(sacc[n][0] - mn0);
                sacc[n][1] = ex2f(sacc[n][1] - mn0);
                sacc[n][2] = ex2f(sacc[n][2] - mn1);
                sacc[n][3] = ex2f(sacc[n][3] - mn1);
                rsum0 += sacc[n][0] + sacc[n][1];
                rsum1 += sacc[n][2] + sacc[n][3];
            }
#pragma unroll
            for (int off = 1; off < 4; off <<= 1) {
                rsum0 += __shfl_xor_sync(0xffffffffu, rsum0, off);
                rsum1 += __shfl_xor_sync(0xffffffffu, rsum1, off);
            }

            m0 = mn0; m1 = mn1;
            l0 = l0 * alpha0 + rsum0;
            l1 = l1 * alpha1 + rsum1;
#pragma unroll
            for (int n = 0; n < 8; ++n) {
                oacc[n][0] *= alpha0; oacc[n][1] *= alpha0;
                oacc[n][2] *= alpha1; oacc[n][3] *= alpha1;
            }

#pragma unroll
            for (int kkp = 0; kkp < 4; ++kkp) {
                float* pa = sacc[2 * kkp];
                float* pb = sacc[2 * kkp + 1];
                uint32_t ph0 = pack_bf16x2(pa[0], pa[1]);
                uint32_t ph1 = pack_bf16x2(pa[2], pa[3]);
                uint32_t ph2 = pack_bf16x2(pb[0], pb[1]);
                uint32_t ph3 = pack_bf16x2(pb[2], pb[3]);
                uint32_t pl0 = pack_bf16x2(pa[0] - bf_lo_f(ph0), pa[1] - bf_hi_f(ph0));
                uint32_t pl1 = pack_bf16x2(pa[2] - bf_lo_f(ph1), pa[3] - bf_hi_f(ph1));
                uint32_t pl2 = pack_bf16x2(pb[0] - bf_lo_f(ph2), pb[1] - bf_hi_f(ph2));
                uint32_t pl3 = pack_bf16x2(pb[2] - bf_lo_f(ph3), pb[3] - bf_hi_f(ph3));
#pragma unroll
                for (int n = 0; n < 8; ++n) {
                    uint4 u = *(const uint4*)&Vsm[(n * 8 + gr) * KPADW + kkp * 16 + 4 * tc];
                    mma_bf16(oacc[n], ph0, ph1, ph2, ph3, u.x, u.y);
                    mma_bf16(oacc[n], pl0, pl1, pl2, pl3, u.x, u.y);
                    mma_bf16(oacc[n], ph0, ph1, ph2, ph3, u.z, u.w);
                }
            }
        }
        __syncthreads();
    }

    float inv0 = 1.f / l0;
    float inv1 = 1.f / l1;
    float* Cg = Ctx + ((size_t)b * Tq + qrow0) * Dq + h * DKq;
    const int r0 = wid * 16 + gr;
#pragma unroll
    for (int n = 0; n < 8; ++n) {
        int c = n * 8 + 2 * tc;
        float2 v0, v1;
        v0.x = oacc[n][0] * inv0; v0.y = oacc[n][1] * inv0;
        v1.x = oacc[n][2] * inv1; v1.y = oacc[n][3] * inv1;
        *(float2*)(Cg + (size_t)r0 * Dq + c)       = v0;
        *(float2*)(Cg + (size_t)(r0 + 8) * Dq + c) = v1;
    }
}

// ---------------- launch ----------------------------------------------------
extern "C" void kernel_launch(void* const* d_in, const int* in_sizes, int n_in,
                              void* d_out, int out_size)
{
    const float* x  = (const float*)d_in[0];
    const float* Wq = (const float*)d_in[1];
    const float* bq = (const float*)d_in[2];
    const float* Wk = (const float*)d_in[3];
    const float* bk = (const float*)d_in[4];
    const float* Wv = (const float*)d_in[5];
    const float* bv = (const float*)d_in[6];
    const float* Wo = (const float*)d_in[7];
    const float* bo = (const float*)d_in[8];
    float* out = (float*)d_out;

    float *pQ, *pV, *pC;
    uint32_t *pKhl, *pVhl;
    cudaGetSymbolAddress((void**)&pQ, g_Q);
    cudaGetSymbolAddress((void**)&pV, g_V);
    cudaGetSymbolAddress((void**)&pC, g_C);
    cudaGetSymbolAddress((void**)&pKhl, g_Khl);
    cudaGetSymbolAddress((void**)&pVhl, g_Vhl);

    dim3 bGemm(128);

    // Q/K/V projections (K written merged pre-split + pair-permuted)
    dim3 gQKV(Dq / GBN, Mq / GBM, 3);
    tf32_qkv_kernel<<<gQKV, bGemm>>>(x, Wq, bq, Wk, bk, Wv, bv, pQ, pKhl, pV);

    // transpose-split V per head (merged interleaved)
    dim3 gTV(Tq / 32, DKq / 32, Hq * Bq);   // (64, 2, 32)
    transpose_split_v_kernel<<<gTV, 256>>>(pV, pVhl);

    // attention (128-thread CTAs, 4/SM, LDS.128 fragments, exp2 softmax)
    dim3 gAttn(Tq / AQT, Hq, Bq);    // (32, 16, 2)
    attn_bf_kernel<<<gAttn, 128>>>(pQ, pKhl, pVhl, pC);

    // output projection
    dim3 gGemm(Dq / GBN, Mq / GBM);
    tf32_gemm_kernel<<<gGemm, bGemm>>>(pC, Wo, bo, out, Mq, Dq, Dq);
}

// round 17
// speedup vs baseline: 1.0482x; 1.0482x over previous
#include <cuda_runtime.h>
#include <cuda_bf16.h>
#include <math.h>
#include <stdint.h>

// Problem constants
#define Bq 2
#define Tq 2048
#define Dq 1024
#define Hq 16
#define DKq 64
#define Mq (Bq*Tq)   // 4096

// ---------------- scratch (device globals; no allocation allowed) ----------
__device__ float g_Q[Mq * Dq];
__device__ float g_V[Mq * Dq];
__device__ float g_C[Mq * Dq];
__device__ __nv_bfloat16 g_Kh[Mq * Dq];    // K hi, (B,T,D), pair-permuted per head
__device__ __nv_bfloat16 g_Kl[Mq * Dq];    // K lo, pair-permuted
__device__ __nv_bfloat16 g_Vth[Mq * Dq];   // V hi, (B,H,DK,T), pair-permuted per 64-key blk
__device__ __nv_bfloat16 g_Vtl[Mq * Dq];   // V lo, pair-permuted

// pair permutation: dpair index p (0..31) -> j' so frag pairs (tc, tc+4) are adjacent
__device__ __forceinline__ int pair_perm(int p) {
    return ((p >> 3) << 3) + 2 * (p & 3) + ((p >> 2) & 1);
}

// ---------------- tf32 helpers ----------------------------------------------
__device__ __forceinline__ uint32_t f2tf32(float f) {
    uint32_t r;
    asm volatile("cvt.rna.tf32.f32 %0, %1;" : "=r"(r) : "f"(f));
    return r;
}

__device__ __forceinline__ void mma_tf32(float c[4],
                                         uint32_t a0, uint32_t a1, uint32_t a2, uint32_t a3,
                                         uint32_t b0, uint32_t b1) {
    asm volatile(
        "mma.sync.aligned.m16n8k8.row.col.f32.tf32.tf32.f32 "
        "{%0,%1,%2,%3}, {%4,%5,%6,%7}, {%8,%9}, {%0,%1,%2,%3};"
        : "+f"(c[0]), "+f"(c[1]), "+f"(c[2]), "+f"(c[3])
        : "r"(a0), "r"(a1), "r"(a2), "r"(a3), "r"(b0), "r"(b1));
}

// ---------------- bf16 helpers ----------------------------------------------
__device__ __forceinline__ uint32_t pack_bf16x2(float x, float y) {
    uint32_t r;
    asm("cvt.rn.bf16x2.f32 %0, %1, %2;" : "=r"(r) : "f"(y), "f"(x));
    return r;
}
__device__ __forceinline__ float bf_lo_f(uint32_t p) { return __uint_as_float(p << 16); }
__device__ __forceinline__ float bf_hi_f(uint32_t p) { return __uint_as_float(p & 0xffff0000u); }

__device__ __forceinline__ void mma_bf16(float c[4],
                                         uint32_t a0, uint32_t a1, uint32_t a2, uint32_t a3,
                                         uint32_t b0, uint32_t b1) {
    asm volatile(
        "mma.sync.aligned.m16n8k16.row.col.f32.bf16.bf16.f32 "
        "{%0,%1,%2,%3}, {%4,%5,%6,%7}, {%8,%9}, {%0,%1,%2,%3};"
        : "+f"(c[0]), "+f"(c[1]), "+f"(c[2]), "+f"(c[3])
        : "r"(a0), "r"(a1), "r"(a2), "r"(a3), "r"(b0), "r"(b1));
}

__device__ __forceinline__ float ex2f(float x) {
    float r;
    asm("ex2.approx.f32 %0, %1;" : "=f"(r) : "f"(x));
    return r;
}
#define QSCALE (0.125f * 1.4426950408889634f)   // 1/sqrt(dk) * log2(e)

// ---------------- pre-pass: V transpose-split (pair-permuted output) ---------
__global__ __launch_bounds__(256)
void transpose_split_v_kernel(const float* __restrict__ V,
                              __nv_bfloat16* __restrict__ Vth,
                              __nv_bfloat16* __restrict__ Vtl)
{
    __shared__ float tile[32][33];
    const int t0 = blockIdx.x * 32;
    const int d0 = blockIdx.y * 32;
    const int h  = blockIdx.z & (Hq - 1);
    const int b  = blockIdx.z >> 4;
    const int tx = threadIdx.x & 31, ty = threadIdx.x >> 5;

    const float* src = V + ((size_t)b * Tq + t0) * Dq + h * DKq + d0;
#pragma unroll
    for (int j = ty; j < 32; j += 8)
        tile[j][tx] = src[(size_t)j * Dq + tx];
    __syncthreads();

    __nv_bfloat16* oh = Vth + (((size_t)b * Hq + h) * DKq + d0) * Tq;
    __nv_bfloat16* ol = Vtl + (((size_t)b * Hq + h) * DKq + d0) * Tq;
#pragma unroll
    for (int j = ty; j < 32; j += 8) {
        float v = tile[tx][j];               // element (t = t0+tx, d = d0+j)
        const int t  = t0 + tx;
        const int kp = (t & 63) >> 1;        // keypair within 64-key block
        const int idx = (t >> 6) * 64 + pair_perm(kp) * 2 + (t & 1);
        __nv_bfloat16 hb = __float2bfloat16(v);
        oh[(size_t)j * Tq + idx] = hb;
        ol[(size_t)j * Tq + idx] = __float2bfloat16(v - __bfloat162float(hb));
    }
}

// ---------------- Pipelined TF32 GEMM: 128 threads, warp tile 64x64 ----------
// A stored with in-16-group column permutation so each A-fragment pair is one
// LDS.64 (u64-bank = (4*tc + gr) mod 16, conflict-free per 16-lane phase).
#define GBM 128
#define GBN 128
#define GBK 16
#define SMP 136

__device__ __forceinline__ int aperm(int m) {
    return (m & ~15) | (2 * (m & 7) + ((m >> 3) & 1));
}

template <int SPLIT>
__device__ __forceinline__
void tf32_gemm_body(const float* __restrict__ X,
                    const float* __restrict__ W,
                    const float* __restrict__ bias,
                    float* __restrict__ Y,
                    __nv_bfloat16* __restrict__ Yh,
                    __nv_bfloat16* __restrict__ Yl,
                    int M, int N, int K,
                    int bm, int bn)
{
    __shared__ __align__(16) uint32_t As[2][GBK][SMP];
    __shared__ __align__(16) uint32_t Bs[2][GBK][SMP];

    const int tid  = threadIdx.x;      // 0..127
    const int wid  = tid >> 5;         // 0..3
    const int lane = tid & 31;
    const int gr   = lane >> 2;
    const int tc   = lane & 3;

    const int wm = wid & 1;
    const int wn = wid >> 1;

    const int a_r0 = tid >> 1;
    const int a_kc = (tid & 1) * 8;
    const int b_r0 = tid >> 4;
    const int b_c  = (tid & 15) * 4;

    const float* Xp = X + (size_t)(bm * GBM) * K;
    const float* Wp = W + (size_t)bn * GBN;

    float acc[4][8][4];
#pragma unroll
    for (int i = 0; i < 4; ++i)
#pragma unroll
        for (int j = 0; j < 8; ++j)
#pragma unroll
            for (int f = 0; f < 4; ++f) acc[i][j][f] = 0.f;

    float4 la[2][2], lb[2][2];

    auto loadTile = [&](int k0) {
#pragma unroll
        for (int q = 0; q < 2; ++q) {
            la[q][0] = *(const float4*)(Xp + (size_t)(a_r0 + q * 64) * K + k0 + a_kc);
            la[q][1] = *(const float4*)(Xp + (size_t)(a_r0 + q * 64) * K + k0 + a_kc + 4);
            lb[q][0] = *(const float4*)(Wp + (size_t)(k0 + b_r0 + q * 8) * N + b_c);
            lb[q][1] = *(const float4*)(Wp + (size_t)(k0 + b_r0 + q * 8) * N + b_c + 64);
        }
    };
    auto storeTile = [&](int s) {
#pragma unroll
        for (int q = 0; q < 2; ++q) {
            const int row = aperm(a_r0 + q * 64);
            As[s][a_kc + 0][row] = f2tf32(la[q][0].x);
            As[s][a_kc + 1][row] = f2tf32(la[q][0].y);
            As[s][a_kc + 2][row] = f2tf32(la[q][0].z);
            As[s][a_kc + 3][row] = f2tf32(la[q][0].w);
            As[s][a_kc + 4][row] = f2tf32(la[q][1].x);
            As[s][a_kc + 5][row] = f2tf32(la[q][1].y);
            As[s][a_kc + 6][row] = f2tf32(la[q][1].z);
            As[s][a_kc + 7][row] = f2tf32(la[q][1].w);
            const int br = b_r0 + q * 8;
            uint4 u0, u1;
            u0.x = f2tf32(lb[q][0].x); u0.y = f2tf32(lb[q][0].y);
            u0.z = f2tf32(lb[q][0].z); u0.w = f2tf32(lb[q][0].w);
            u1.x = f2tf32(lb[q][1].x); u1.y = f2tf32(lb[q][1].y);
            u1.z = f2tf32(lb[q][1].z); u1.w = f2tf32(lb[q][1].w);
            *(uint4*)&Bs[s][br][b_c]      = u0;
            *(uint4*)&Bs[s][br][b_c + 64] = u1;
        }
    };

    loadTile(0);
    storeTile(0);
    __syncthreads();

    int cur = 0;
    for (int k0 = 0; k0 < K; k0 += GBK) {
        const bool has_next = (k0 + GBK < K);
        if (has_next) loadTile(k0 + GBK);

#pragma unroll
        for (int ks = 0; ks < GBK; ks += 8) {
            uint32_t af[4][4];
            uint32_t bf[8][2];
#pragma unroll
            for (int mt = 0; mt < 4; ++mt) {
                int m0 = wm * 64 + mt * 16 + 2 * gr;      // permuted pair base
                uint2 p0 = *(const uint2*)&As[cur][ks + tc][m0];
                uint2 p1 = *(const uint2*)&As[cur][ks + tc + 4][m0];
                af[mt][0] = p0.x; af[mt][1] = p0.y;
                af[mt][2] = p1.x; af[mt][3] = p1.y;
            }
#pragma unroll
            for (int nt = 0; nt < 8; ++nt) {
                int n0 = wn * 64 + nt * 8;
                bf[nt][0] = Bs[cur][ks + tc][n0 + gr];
                bf[nt][1] = Bs[cur][ks + tc + 4][n0 + gr];
            }
#pragma unroll
            for (int mt = 0; mt < 4; ++mt)
#pragma unroll
                for (int nt = 0; nt < 8; ++nt)
                    mma_tf32(acc[mt][nt],
                             af[mt][0], af[mt][1], af[mt][2], af[mt][3],
                             bf[nt][0], bf[nt][1]);
        }

        if (has_next) {
            const int nxt = cur ^ 1;
            storeTile(nxt);
            __syncthreads();
            cur = nxt;
        }
    }

#pragma unroll
    for (int mt = 0; mt < 4; ++mt) {
        int row = bm * GBM + wm * 64 + mt * 16 + gr;
#pragma unroll
        for (int nt = 0; nt < 8; ++nt) {
            int col = bn * GBN + wn * 64 + nt * 8 + 2 * tc;
            float b0 = bias[col], b1 = bias[col + 1];
            float v00 = acc[mt][nt][0] + b0, v01 = acc[mt][nt][1] + b1;
            float v10 = acc[mt][nt][2] + b0, v11 = acc[mt][nt][3] + b1;
            if (SPLIT) {
                const int dp  = (col & 63) >> 1;
                const int cj  = (col >> 6) * 32 + pair_perm(dp);
                uint32_t h0 = pack_bf16x2(v00, v01);
                uint32_t l0 = pack_bf16x2(v00 - bf_lo_f(h0), v01 - bf_hi_f(h0));
                uint32_t h1 = pack_bf16x2(v10, v11);
                uint32_t l1 = pack_bf16x2(v10 - bf_lo_f(h1), v11 - bf_hi_f(h1));
                ((uint32_t*)Yh)[(size_t)row * (N >> 1) + cj]       = h0;
                ((uint32_t*)Yl)[(size_t)row * (N >> 1) + cj]       = l0;
                ((uint32_t*)Yh)[(size_t)(row + 8) * (N >> 1) + cj] = h1;
                ((uint32_t*)Yl)[(size_t)(row + 8) * (N >> 1) + cj] = l1;
            } else {
                float2 lo, hi;
                lo.x = v00; lo.y = v01;
                hi.x = v10; hi.y = v11;
                *(float2*)(Y + (size_t)row * N + col)       = lo;
                *(float2*)(Y + (size_t)(row + 8) * N + col) = hi;
            }
        }
    }
}

__global__ __launch_bounds__(128, 2)
void tf32_gemm_kernel(const float* __restrict__ X,
                      const float* __restrict__ W,
                      const float* __restrict__ bias,
                      float* __restrict__ Y,
                      int M, int N, int K)
{
    tf32_gemm_body<0>(X, W, bias, Y, nullptr, nullptr, M, N, K, blockIdx.y, blockIdx.x);
}

__global__ __launch_bounds__(128, 2)
void tf32_qkv_kernel(const float* __restrict__ X,
                     const float* __restrict__ Wq, const float* __restrict__ bqv,
                     const float* __restrict__ Wk, const float* __restrict__ bkv,
                     const float* __restrict__ Wv, const float* __restrict__ bvv,
                     float* __restrict__ Qo,
                     __nv_bfloat16* __restrict__ Kh, __nv_bfloat16* __restrict__ Kl,
                     float* __restrict__ Vo)
{
    if (blockIdx.z == 0)
        tf32_gemm_body<0>(X, Wq, bqv, Qo, nullptr, nullptr, Mq, Dq, Dq, blockIdx.y, blockIdx.x);
    else if (blockIdx.z == 1)
        tf32_gemm_body<1>(X, Wk, bkv, nullptr, Kh, Kl, Mq, Dq, Dq, blockIdx.y, blockIdx.x);
    else
        tf32_gemm_body<0>(X, Wv, bvv, Vo, nullptr, nullptr, Mq, Dq, Dq, blockIdx.y, blockIdx.x);
}

// ---------------- bf16-split flash attention (paired LDS.64 fragments) -------
// R15 champion layout + exp2-domain softmax.
#define AQT 64
#define AKT 64
#define KPADW 40

__global__ __launch_bounds__(128, 4)
void attn_bf_kernel(const float* __restrict__ Q,
                    const __nv_bfloat16* __restrict__ Kh,
                    const __nv_bfloat16* __restrict__ Kl,
                    const __nv_bfloat16* __restrict__ Vth,
                    const __nv_bfloat16* __restrict__ Vtl,
                    float* __restrict__ Ctx)
{
    __shared__ uint32_t Kh32[64 * KPADW];
    __shared__ uint32_t Kl32[64 * KPADW];
    __shared__ uint32_t Vh32[64 * KPADW];
    __shared__ uint32_t Vl32[64 * KPADW];

    const int b  = blockIdx.z;
    const int h  = blockIdx.y;
    const int qb = gridDim.x - 1 - blockIdx.x;
    const int tid  = threadIdx.x;
    const int wid  = tid >> 5;
    const int lane = tid & 31;
    const int gr   = lane >> 2;
    const int tc   = lane & 3;

    const int qrow0 = qb * AQT;
    const float* Qg = Q + ((size_t)b * Tq + qrow0) * Dq + h * DKq;

    uint32_t qh[4][4], ql[4][4];
    {
        const int rbase = wid * 16;
#pragma unroll
        for (int kk = 0; kk < 4; ++kk) {
#pragma unroll
            for (int f = 0; f < 4; ++f) {
                int r = rbase + gr + (f & 1) * 8;
                int c = kk * 16 + 2 * tc + (f >> 1) * 8;
                float2 v = *(const float2*)(Qg + (size_t)r * Dq + c);
                v.x *= QSCALE; v.y *= QSCALE;   // exp2-domain scale
                uint32_t hpk = pack_bf16x2(v.x, v.y);
                qh[kk][f] = hpk;
                ql[kk][f] = pack_bf16x2(v.x - bf_lo_f(hpk), v.y - bf_hi_f(hpk));
            }
        }
    }

    float oacc[8][4];
#pragma unroll
    for (int n = 0; n < 8; ++n)
#pragma unroll
        for (int f = 0; f < 4; ++f) oacc[n][f] = 0.f;
    float m0 = -INFINITY, m1 = -INFINITY, l0 = 0.f, l1 = 0.f;

    const int row0g = qrow0 + wid * 16 + gr;
    const int row1g = row0g + 8;
    const int kbmax = qb + 1;

    for (int kb = 0; kb < kbmax; ++kb) {
        {
            const __nv_bfloat16* Kgh = Kh + ((size_t)b * Tq + kb * AKT) * Dq + h * DKq;
            const __nv_bfloat16* Kgl = Kl + ((size_t)b * Tq + kb * AKT) * Dq + h * DKq;
            const __nv_bfloat16* Vgh = Vth + (((size_t)b * Hq + h) * DKq) * Tq + kb * AKT;
            const __nv_bfloat16* Vgl = Vtl + (((size_t)b * Hq + h) * DKq) * Tq + kb * AKT;
#pragma unroll
            for (int i = tid; i < 512; i += 128) {
                int r = i >> 3, j = i & 7;
                *(uint4*)&Kh32[r * KPADW + j * 4] = *(const uint4*)(Kgh + (size_t)r * Dq + j * 8);
                *(uint4*)&Kl32[r * KPADW + j * 4] = *(const uint4*)(Kgl + (size_t)r * Dq + j * 8);
                *(uint4*)&Vh32[r * KPADW + j * 4] = *(const uint4*)(Vgh + (size_t)r * Tq + j * 8);
                *(uint4*)&Vl32[r * KPADW + j * 4] = *(const uint4*)(Vgl + (size_t)r * Tq + j * 8);
            }
        }
        __syncthreads();

        {
            float sacc[8][4];
#pragma unroll
            for (int n = 0; n < 8; ++n)
#pragma unroll
                for (int f = 0; f < 4; ++f) sacc[n][f] = 0.f;

#pragma unroll
            for (int kk = 0; kk < 4; ++kk) {
#pragma unroll
                for (int n = 0; n < 8; ++n) {
                    int base = (n * 8 + gr) * KPADW + kk * 8 + 2 * tc;
                    uint2 bh = *(const uint2*)&Kh32[base];
                    uint2 bl = *(const uint2*)&Kl32[base];
                    mma_bf16(sacc[n], qh[kk][0], qh[kk][1], qh[kk][2], qh[kk][3], bh.x, bh.y);
                    mma_bf16(sacc[n], ql[kk][0], ql[kk][1], ql[kk][2], ql[kk][3], bh.x, bh.y);
                    mma_bf16(sacc[n], qh[kk][0], qh[kk][1], qh[kk][2], qh[kk][3], bl.x, bl.y);
                }
            }

            if (kb == kbmax - 1) {
#pragma unroll
                for (int n = 0; n < 8; ++n) {
                    int colg = kb * AKT + n * 8 + 2 * tc;
                    if (colg     > row0g) sacc[n][0] = -INFINITY;
                    if (colg + 1 > row0g) sacc[n][1] = -INFINITY;
                    if (colg     > row1g) sacc[n][2] = -INFINITY;
                    if (colg + 1 > row1g) sacc[n][3] = -INFINITY;
                }
            }

            float rmax0 = -INFINITY, rmax1 = -INFINITY;
#pragma unroll
            for (int n = 0; n < 8; ++n) {
                rmax0 = fmaxf(rmax0, fmaxf(sacc[n][0], sacc[n][1]));
                rmax1 = fmaxf(rmax1, fmaxf(sacc[n][2], sacc[n][3]));
            }
#pragma unroll
            for (int off = 1; off < 4; off <<= 1) {
                rmax0 = fmaxf(rmax0, __shfl_xor_sync(0xffffffffu, rmax0, off));
                rmax1 = fmaxf(rmax1, __shfl_xor_sync(0xffffffffu, rmax1, off));
            }

            float mn0 = fmaxf(m0, rmax0);
            float mn1 = fmaxf(m1, rmax1);
            float alpha0 = ex2f(m0 - mn0);
            float alpha1 = ex2f(m1 - mn1);

            float rsum0 = 0.f, rsum1 = 0.f;
#pragma unroll
            for (int n = 0; n < 8; ++n) {
                sacc[n][0] = ex2f(sacc[n][0] - mn0);
                sacc[n][1] = ex2f(sacc[n][1] - mn0);
                sacc[n][2] = ex2f(sacc[n][2] - mn1);
                sacc[n][3] = ex2f(sacc[n][3] - mn1);
                rsum0 += sacc[n][0] + sacc[n][1];
                rsum1 += sacc[n][2] + sacc[n][3];
            }
#pragma unroll
            for (int off = 1; off < 4; off <<= 1) {
                rsum0 += __shfl_xor_sync(0xffffffffu, rsum0, off);
                rsum1 += __shfl_xor_sync(0xffffffffu, rsum1, off);
            }

            m0 = mn0; m1 = mn1;
            l0 = l0 * alpha0 + rsum0;
            l1 = l1 * alpha1 + rsum1;
#pragma unroll
            for (int n = 0; n < 8; ++n) {
                oacc[n][0] *= alpha0; oacc[n][1] *= alpha0;
                oacc[n][2] *= alpha1; oacc[n][3] *= alpha1;
            }

#pragma unroll
            for (int kkp = 0; kkp < 4; ++kkp) {
                float* pa = sacc[2 * kkp];
                float* pb = sacc[2 * kkp + 1];
                uint32_t ph0 = pack_bf16x2(pa[0], pa[1]);
                uint32_t ph1 = pack_bf16x2(pa[2], pa[3]);
                uint32_t ph2 = pack_bf16x2(pb[0], pb[1]);
                uint32_t ph3 = pack_bf16x2(pb[2], pb[3]);
                uint32_t pl0 = pack_bf16x2(pa[0] - bf_lo_f(ph0), pa[1] - bf_hi_f(ph0));
                uint32_t pl1 = pack_bf16x2(pa[2] - bf_lo_f(ph1), pa[3] - bf_hi_f(ph1));
                uint32_t pl2 = pack_bf16x2(pb[0] - bf_lo_f(ph2), pb[1] - bf_hi_f(ph2));
                uint32_t pl3 = pack_bf16x2(pb[2] - bf_lo_f(ph3), pb[3] - bf_hi_f(ph3));
#pragma unroll
                for (int n = 0; n < 8; ++n) {
                    int base = (n * 8 + gr) * KPADW + kkp * 8 + 2 * tc;
                    uint2 bh = *(const uint2*)&Vh32[base];
                    uint2 bl = *(const uint2*)&Vl32[base];
                    mma_bf16(oacc[n], ph0, ph1, ph2, ph3, bh.x, bh.y);
                    mma_bf16(oacc[n], pl0, pl1, pl2, pl3, bh.x, bh.y);
                    mma_bf16(oacc[n], ph0, ph1, ph2, ph3, bl.x, bl.y);
                }
            }
        }
        __syncthreads();
    }

    float inv0 = 1.f / l0;
    float inv1 = 1.f / l1;
    float* Cg = Ctx + ((size_t)b * Tq + qrow0) * Dq + h * DKq;
    const int r0 = wid * 16 + gr;
#pragma unroll
    for (int n = 0; n < 8; ++n) {
        int c = n * 8 + 2 * tc;
        float2 v0, v1;
        v0.x = oacc[n][0] * inv0; v0.y = oacc[n][1] * inv0;
        v1.x = oacc[n][2] * inv1; v1.y = oacc[n][3] * inv1;
        *(float2*)(Cg + (size_t)r0 * Dq + c)       = v0;
        *(float2*)(Cg + (size_t)(r0 + 8) * Dq + c) = v1;
    }
}

// ---------------- launch ----------------------------------------------------
extern "C" void kernel_launch(void* const* d_in, const int* in_sizes, int n_in,
                              void* d_out, int out_size)
{
    const float* x  = (const float*)d_in[0];
    const float* Wq = (const float*)d_in[1];
    const float* bq = (const float*)d_in[2];
    const float* Wk = (const float*)d_in[3];
    const float* bk = (const float*)d_in[4];
    const float* Wv = (const float*)d_in[5];
    const float* bv = (const float*)d_in[6];
    const float* Wo = (const float*)d_in[7];
    const float* bo = (const float*)d_in[8];
    float* out = (float*)d_out;

    float *pQ, *pV, *pC;
    __nv_bfloat16 *pKh, *pKl, *pVth, *pVtl;
    cudaGetSymbolAddress((void**)&pQ, g_Q);
    cudaGetSymbolAddress((void**)&pV, g_V);
    cudaGetSymbolAddress((void**)&pC, g_C);
    cudaGetSymbolAddress((void**)&pKh, g_Kh);
    cudaGetSymbolAddress((void**)&pKl, g_Kl);
    cudaGetSymbolAddress((void**)&pVth, g_Vth);
    cudaGetSymbolAddress((void**)&pVtl, g_Vtl);

    dim3 bGemm(128);

    // Q/K/V projections (K written pre-split + pair-permuted)
    dim3 gQKV(Dq / GBN, Mq / GBM, 3);
    tf32_qkv_kernel<<<gQKV, bGemm>>>(x, Wq, bq, Wk, bk, Wv, bv, pQ, pKh, pKl, pV);

    // transpose-split V per head (pair-permuted)
    dim3 gTV(Tq / 32, DKq / 32, Hq * Bq);   // (64, 2, 32)
    transpose_split_v_kernel<<<gTV, 256>>>(pV, pVth, pVtl);

    // attention (128-thread CTAs, 4/SM, LDS.64 fragments, exp2 softmax)
    dim3 gAttn(Tq / AQT, Hq, Bq);    // (32, 16, 2)
    attn_bf_kernel<<<gAttn, 128>>>(pQ, pKh, pKl, pVth, pVtl, pC);

    // output projection
    dim3 gGemm(Dq / GBN, Mq / GBM);
    tf32_gemm_kernel<<<gGemm, bGemm>>>(pC, Wo, bo, out, Mq, Dq, Dq);
}